// round 9
// baseline (speedup 1.0000x reference)
#include <cuda_runtime.h>
#include <cstdint>

#define C_INN 128
#define C_OUTT 64
#define BB 8
#define NN 2048
#define LOG2E 1.4426950408889634f

// ---------------------------------------------------------------------------
// Scratch (__device__ globals: allocation-free per harness rules)
// ---------------------------------------------------------------------------
__device__ float  g_Wh[BB * NN * C_OUTT];       // tf32-rounded Wh, 4 MB
__device__ float2 g_E1i[BB * NN];               // {exp(f1), exp(0.2 f1)}
__device__ float2 g_E2i[BB * NN];               // {exp(f2), exp(0.2 f2)}
__device__ unsigned g_Mt[(NN / 32) * NN];       // transposed bitmask [word][i]

__device__ __forceinline__ float fast_exp(float x) {
    float r;
    asm("ex2.approx.f32 %0, %1;" : "=f"(r) : "f"(x * LOG2E));
    return r;
}
__device__ __forceinline__ uint32_t cvt_tf32(float f) {
    uint32_t u;
    asm("cvt.rna.tf32.f32 %0, %1;" : "=r"(u) : "f"(f));
    return u;
}
__device__ __forceinline__ float tf32f(float f) {
    return __uint_as_float(cvt_tf32(f));
}
__device__ __forceinline__ uint32_t smem_u32(const void* p) {
    return (uint32_t)__cvta_generic_to_shared(p);
}
__device__ __forceinline__ void cpa16(uint32_t d, const void* s) {
    asm volatile("cp.async.cg.shared.global [%0], [%1], 16;" :: "r"(d), "l"(s));
}
__device__ __forceinline__ void cpa8(uint32_t d, const void* s) {
    asm volatile("cp.async.ca.shared.global [%0], [%1], 8;" :: "r"(d), "l"(s));
}
__device__ __forceinline__ void cpa4(uint32_t d, const void* s) {
    asm volatile("cp.async.ca.shared.global [%0], [%1], 4;" :: "r"(d), "l"(s));
}
__device__ __forceinline__ void cpa_commit() {
    asm volatile("cp.async.commit_group;" ::: "memory");
}
__device__ __forceinline__ void cpa_wait0() {
    asm volatile("cp.async.wait_group 0;" ::: "memory");
}

// ---------------------------------------------------------------------------
// Kernel 1: Wh = x @ W via tf32 mma.sync (R8 version, 13.8us measured).
// ---------------------------------------------------------------------------
__global__ void __launch_bounds__(256) k_wh(const float* __restrict__ x,
                                            const float* __restrict__ W,
                                            const float* __restrict__ attn)
{
    extern __shared__ float sm[];
    float*  xs  = sm;                       // 64 x 132
    float*  Ws  = sm + 64 * 132;            // 128 x 72
    float2* w12 = (float2*)(Ws + 128 * 72); // 128 x {w1,w2}

    int t = threadIdx.x, wid = t >> 5, lane = t & 31;
    int g = lane >> 2, tk = lane & 3;
    int warpM = wid >> 1, warpN = wid & 1;
    int base = blockIdx.x * 64;

    {
        const float4* xr = (const float4*)(x + (size_t)base * C_INN);
        #pragma unroll
        for (int k = 0; k < 8; k++) {
            int i4 = t + k * 256;
            float4 v = xr[i4];
            int row = i4 >> 5, c = (i4 & 31) << 2;
            *(float4*)&xs[row * 132 + c] =
                make_float4(tf32f(v.x), tf32f(v.y), tf32f(v.z), tf32f(v.w));
        }
    }
    {
        const float4* wr = (const float4*)W;
        #pragma unroll
        for (int k = 0; k < 8; k++) {
            int i4 = t + k * 256;
            float4 v = wr[i4];
            int c = i4 >> 4, n = (i4 & 15) << 2;
            *(float4*)&Ws[c * 72 + n] =
                make_float4(tf32f(v.x), tf32f(v.y), tf32f(v.z), tf32f(v.w));
        }
    }
    __syncthreads();

    if (t < 128) {
        float w1 = 0.f, w2 = 0.f;
        const float* wrow = Ws + t * 72;
        #pragma unroll 8
        for (int n = 0; n < 64; n++) {
            float wv = wrow[n];
            w1 = fmaf(wv, attn[n], w1);
            w2 = fmaf(wv, attn[64 + n], w2);
        }
        w12[t] = make_float2(w1, w2);
    }
    __syncthreads();

    int r0 = warpM * 16;
    float acc[4][4];
    #pragma unroll
    for (int nt = 0; nt < 4; nt++)
        #pragma unroll
        for (int k = 0; k < 4; k++) acc[nt][k] = 0.f;

    #pragma unroll
    for (int ks = 0; ks < 16; ks++) {
        int c0 = ks * 8;
        uint32_t a0 = __float_as_uint(xs[(r0 + g) * 132 + c0 + tk]);
        uint32_t a1 = __float_as_uint(xs[(r0 + g + 8) * 132 + c0 + tk]);
        uint32_t a2 = __float_as_uint(xs[(r0 + g) * 132 + c0 + tk + 4]);
        uint32_t a3 = __float_as_uint(xs[(r0 + g + 8) * 132 + c0 + tk + 4]);
        const float* brow = Ws + (c0 + tk) * 72 + warpN * 32 + g;
        #pragma unroll
        for (int nt = 0; nt < 4; nt++) {
            uint32_t ub0 = __float_as_uint(brow[nt * 8]);
            uint32_t ub1 = __float_as_uint(brow[288 + nt * 8]);
            asm volatile(
                "mma.sync.aligned.m16n8k8.row.col.f32.tf32.tf32.f32 "
                "{%0,%1,%2,%3}, {%4,%5,%6,%7}, {%8,%9}, {%0,%1,%2,%3};"
                : "+f"(acc[nt][0]), "+f"(acc[nt][1]), "+f"(acc[nt][2]), "+f"(acc[nt][3])
                : "r"(a0), "r"(a1), "r"(a2), "r"(a3), "r"(ub0), "r"(ub1));
        }
    }

    {
        int row = t >> 2, q = t & 3;
        const float4* xv4 = (const float4*)&xs[row * 132 + q * 32];
        const float4* wv4 = (const float4*)(w12 + q * 32);
        float f1 = 0.f, f2 = 0.f;
        #pragma unroll
        for (int k = 0; k < 8; k++) {
            float4 xv = xv4[k];
            float4 wa = wv4[2 * k], wb = wv4[2 * k + 1];
            f1 += xv.x * wa.x + xv.y * wa.z + xv.z * wb.x + xv.w * wb.z;
            f2 += xv.x * wa.y + xv.y * wa.w + xv.z * wb.y + xv.w * wb.w;
        }
        f1 += __shfl_xor_sync(0xffffffffu, f1, 1);
        f1 += __shfl_xor_sync(0xffffffffu, f1, 2);
        f2 += __shfl_xor_sync(0xffffffffu, f2, 1);
        f2 += __shfl_xor_sync(0xffffffffu, f2, 2);
        if (q == 0) {
            int gr = base + row;
            g_E1i[gr] = make_float2(fast_exp(f1), fast_exp(0.2f * f1));
            g_E2i[gr] = make_float2(fast_exp(f2), fast_exp(0.2f * f2));
        }
    }

    #pragma unroll
    for (int nt = 0; nt < 4; nt++) {
        int n = warpN * 32 + nt * 8 + tk * 2;
        *(float2*)&g_Wh[(size_t)(base + r0 + g) * C_OUTT + n] =
            make_float2(tf32f(acc[nt][0]), tf32f(acc[nt][1]));
        *(float2*)&g_Wh[(size_t)(base + r0 + g + 8) * C_OUTT + n] =
            make_float2(tf32f(acc[nt][2]), tf32f(acc[nt][3]));
    }
}

// ---------------------------------------------------------------------------
// Kernel 2: bit-pack mask, stored TRANSPOSED: g_Mt[word][i].
// ---------------------------------------------------------------------------
__global__ void __launch_bounds__(256) k_mask(const int* __restrict__ A)
{
    __shared__ unsigned char nib[256];
    int t = threadIdx.x;
    int i = blockIdx.x >> 1;
    int wb = (blockIdx.x & 1) * 32;
    int4 v = ((const int4*)A)[(size_t)blockIdx.x * 256 + t];
    unsigned n = (v.x > 0 ? 1u : 0u) | (v.y > 0 ? 2u : 0u) |
                 (v.z > 0 ? 4u : 0u) | (v.w > 0 ? 8u : 0u);
    nib[t] = (unsigned char)n;
    __syncthreads();
    if (t < 32) {
        const unsigned char* p = nib + t * 8;
        unsigned w = 0;
        #pragma unroll
        for (int s = 0; s < 8; s++) w |= ((unsigned)(p[s] & 0xFu)) << (4 * s);
        g_Mt[(size_t)(wb + t) * NN + i] = w;
    }
}

// ---------------------------------------------------------------------------
// Kernel 3: fused P-build + tf32 mma aggregation.
// 512 thr = 16 warps = 4 warpM (M=32 each) x 4 kwarp (4 k-steps each/jt).
// M=32/warp halves B-fragment crossbar traffic vs M=16 (the R5 bottleneck).
// 2-stage cp.async pipeline over double-buffered SMEM tiles (one sync/jt).
// Epilogue: 2-round tree reduction of the 4 kwarp partials through SMEM.
// ---------------------------------------------------------------------------
#define BUF_BYTES 39936          // Whs 36864 + E2s 1024 + Msh 2048
#define GAT_SMEM  (2 * BUF_BYTES)

__global__ void __launch_bounds__(512, 1) k_gat(float* __restrict__ out)
{
    extern __shared__ char dsm[];

    int t = threadIdx.x;
    int lane = t & 31, w = t >> 5;
    int warpM = w >> 2, kwarp = w & 3;
    int g = lane >> 2, tk = lane & 3;
    int b = blockIdx.x >> 4, i0 = (blockIdx.x & 15) << 7;
    int b2048 = b * NN;

    float2 e1[4];
    #pragma unroll
    for (int m = 0; m < 4; m++)
        e1[m] = g_E1i[b2048 + i0 + warpM * 32 + g + m * 8];

    float cA[8][4], cB[8][4];
    #pragma unroll
    for (int nt = 0; nt < 8; nt++)
        #pragma unroll
        for (int k = 0; k < 4; k++) { cA[nt][k] = 0.f; cB[nt][k] = 0.f; }
    float z0 = 0.f, z1 = 0.f, z2 = 0.f, z3 = 0.f;

    const float4* wh4 = (const float4*)(g_Wh + (size_t)b2048 * C_OUTT);
    uint32_t smb = smem_u32(dsm);

    // stage a tile into buffer `bi` (cp.async, no regs)
    auto stage = [&](int jt, int bi) {
        uint32_t wb_ = smb + bi * BUF_BYTES;
        const float4* src = wh4 + jt * 2048;
        #pragma unroll
        for (int k = 0; k < 4; k++) {
            int idx = t + k * 512;
            cpa16(wb_ + (uint32_t)((idx >> 4) * 72 + ((idx & 15) << 2)) * 4u,
                  src + idx);
        }
        // mask: 512 words, one per thread
        cpa4(wb_ + 37888u + (uint32_t)t * 4u,
             &g_Mt[(size_t)(jt * 4 + (t >> 7)) * NN + i0 + (t & 127)]);
        // E2 pairs: 128 float2
        if (t < 128)
            cpa8(wb_ + 36864u + (uint32_t)t * 8u, &g_E2i[b2048 + jt * 128 + t]);
        cpa_commit();
    };

    stage(0, 0);

    for (int jt = 0; jt < 16; jt++) {
        cpa_wait0();
        __syncthreads();                 // tile jt visible everywhere; jt-1 compute done
        stage((jt + 1) & 15, (jt + 1) & 1);   // prefetch overlaps compute below

        const char* buf = dsm + (jt & 1) * BUF_BYTES;
        const float*    Whs = (const float*)buf;
        const float2*   E2s = (const float2*)(buf + 36864);
        const unsigned* Msh = (const unsigned*)(buf + 37888);  // [4][128]

        unsigned mw0 = Msh[kwarp * 128 + warpM * 32 + g];
        unsigned mw1 = Msh[kwarp * 128 + warpM * 32 + g + 8];
        unsigned mw2 = Msh[kwarp * 128 + warpM * 32 + g + 16];
        unsigned mw3 = Msh[kwarp * 128 + warpM * 32 + g + 24];

        #pragma unroll
        for (int ksl = 0; ksl < 4; ksl++) {
            int j0 = (kwarp * 4 + ksl) * 8;
            float2 ea = E2s[j0 + tk];
            float2 eb = E2s[j0 + tk + 4];
            unsigned s0 = (1u << tk) << (ksl * 8);
            unsigned s1 = s0 << 4;

            float m;
            m = fmaxf(e1[0].x * ea.x, e1[0].y * ea.y);
            float pA0 = (mw0 & s0) ? m : 0.f;
            m = fmaxf(e1[1].x * ea.x, e1[1].y * ea.y);
            float pA1 = (mw1 & s0) ? m : 0.f;
            m = fmaxf(e1[0].x * eb.x, e1[0].y * eb.y);
            float pA2 = (mw0 & s1) ? m : 0.f;
            m = fmaxf(e1[1].x * eb.x, e1[1].y * eb.y);
            float pA3 = (mw1 & s1) ? m : 0.f;
            m = fmaxf(e1[2].x * ea.x, e1[2].y * ea.y);
            float pB0 = (mw2 & s0) ? m : 0.f;
            m = fmaxf(e1[3].x * ea.x, e1[3].y * ea.y);
            float pB1 = (mw3 & s0) ? m : 0.f;
            m = fmaxf(e1[2].x * eb.x, e1[2].y * eb.y);
            float pB2 = (mw2 & s1) ? m : 0.f;
            m = fmaxf(e1[3].x * eb.x, e1[3].y * eb.y);
            float pB3 = (mw3 & s1) ? m : 0.f;

            z0 += pA0 + pA2; z1 += pA1 + pA3;
            z2 += pB0 + pB2; z3 += pB1 + pB3;

            uint32_t uA0 = __float_as_uint(pA0), uA1 = __float_as_uint(pA1);
            uint32_t uA2 = __float_as_uint(pA2), uA3 = __float_as_uint(pA3);
            uint32_t uB0 = __float_as_uint(pB0), uB1 = __float_as_uint(pB1);
            uint32_t uB2 = __float_as_uint(pB2), uB3 = __float_as_uint(pB3);

            const float* brow = Whs + (j0 + tk) * 72 + g;
            #pragma unroll
            for (int nt = 0; nt < 8; nt++) {
                uint32_t ub0 = __float_as_uint(brow[nt * 8]);
                uint32_t ub1 = __float_as_uint(brow[288 + nt * 8]);
                asm volatile(
                    "mma.sync.aligned.m16n8k8.row.col.f32.tf32.tf32.f32 "
                    "{%0,%1,%2,%3}, {%4,%5,%6,%7}, {%8,%9}, {%0,%1,%2,%3};"
                    : "+f"(cA[nt][0]), "+f"(cA[nt][1]), "+f"(cA[nt][2]), "+f"(cA[nt][3])
                    : "r"(uA0), "r"(uA1), "r"(uA2), "r"(uA3), "r"(ub0), "r"(ub1));
                asm volatile(
                    "mma.sync.aligned.m16n8k8.row.col.f32.tf32.tf32.f32 "
                    "{%0,%1,%2,%3}, {%4,%5,%6,%7}, {%8,%9}, {%0,%1,%2,%3};"
                    : "+f"(cB[nt][0]), "+f"(cB[nt][1]), "+f"(cB[nt][2]), "+f"(cB[nt][3])
                    : "r"(uB0), "r"(uB1), "r"(uB2), "r"(uB3), "r"(ub0), "r"(ub1));
            }
        }
    }

    // drain in-flight prefetch, then reuse SMEM for reduction
    cpa_wait0();
    __syncthreads();

    // tk-lane reduce of z (lane = g*4+tk; xor 1,2 mixes tk only)
    z0 += __shfl_xor_sync(0xffffffffu, z0, 1);
    z0 += __shfl_xor_sync(0xffffffffu, z0, 2);
    z1 += __shfl_xor_sync(0xffffffffu, z1, 1);
    z1 += __shfl_xor_sync(0xffffffffu, z1, 2);
    z2 += __shfl_xor_sync(0xffffffffu, z2, 1);
    z2 += __shfl_xor_sync(0xffffffffu, z2, 2);
    z3 += __shfl_xor_sync(0xffffffffu, z3, 1);
    z3 += __shfl_xor_sync(0xffffffffu, z3, 2);

    float4* A4  = (float4*)(dsm);
    float4* B4  = (float4*)(dsm + 32768);
    float4* zA4 = (float4*)(dsm + 65536);
    float4* zB4 = (float4*)(dsm + 67584);
    int slot = warpM * 32 + lane;

    // round 1: kwarp 1 -> A, kwarp 3 -> B
    if (kwarp == 1 || kwarp == 3) {
        float4* D  = (kwarp == 1) ? A4 : B4;
        float4* Dz = (kwarp == 1) ? zA4 : zB4;
        #pragma unroll
        for (int nt = 0; nt < 8; nt++) {
            D[nt * 128 + slot] = make_float4(cA[nt][0], cA[nt][1], cA[nt][2], cA[nt][3]);
            D[(8 + nt) * 128 + slot] = make_float4(cB[nt][0], cB[nt][1], cB[nt][2], cB[nt][3]);
        }
        Dz[slot] = make_float4(z0, z1, z2, z3);
    }
    __syncthreads();
    if (kwarp == 0 || kwarp == 2) {
        float4* S  = (kwarp == 0) ? A4 : B4;
        float4* Sz = (kwarp == 0) ? zA4 : zB4;
        #pragma unroll
        for (int nt = 0; nt < 8; nt++) {
            float4 v = S[nt * 128 + slot];
            cA[nt][0] += v.x; cA[nt][1] += v.y; cA[nt][2] += v.z; cA[nt][3] += v.w;
            float4 u = S[(8 + nt) * 128 + slot];
            cB[nt][0] += u.x; cB[nt][1] += u.y; cB[nt][2] += u.z; cB[nt][3] += u.w;
        }
        float4 zz = Sz[slot];
        z0 += zz.x; z1 += zz.y; z2 += zz.z; z3 += zz.w;
    }
    __syncthreads();
    // round 2: kwarp 2 -> A
    if (kwarp == 2) {
        #pragma unroll
        for (int nt = 0; nt < 8; nt++) {
            A4[nt * 128 + slot] = make_float4(cA[nt][0], cA[nt][1], cA[nt][2], cA[nt][3]);
            A4[(8 + nt) * 128 + slot] = make_float4(cB[nt][0], cB[nt][1], cB[nt][2], cB[nt][3]);
        }
        zA4[slot] = make_float4(z0, z1, z2, z3);
    }
    __syncthreads();
    if (kwarp == 0) {
        #pragma unroll
        for (int nt = 0; nt < 8; nt++) {
            float4 v = A4[nt * 128 + slot];
            cA[nt][0] += v.x; cA[nt][1] += v.y; cA[nt][2] += v.z; cA[nt][3] += v.w;
            float4 u = A4[(8 + nt) * 128 + slot];
            cB[nt][0] += u.x; cB[nt][1] += u.y; cB[nt][2] += u.z; cB[nt][3] += u.w;
        }
        float4 zz = zA4[slot];
        float inv0 = 1.f / (z0 + zz.x);
        float inv1 = 1.f / (z1 + zz.y);
        float inv2 = 1.f / (z2 + zz.z);
        float inv3 = 1.f / (z3 + zz.w);

        int rbase = b2048 + i0 + warpM * 32 + g;
        float* o0 = out + (size_t)(rbase)      * C_OUTT + tk * 2;
        float* o1 = out + (size_t)(rbase + 8)  * C_OUTT + tk * 2;
        float* o2 = out + (size_t)(rbase + 16) * C_OUTT + tk * 2;
        float* o3 = out + (size_t)(rbase + 24) * C_OUTT + tk * 2;
        #pragma unroll
        for (int nt = 0; nt < 8; nt++) {
            *(float2*)(o0 + nt * 8) = make_float2(cA[nt][0] * inv0, cA[nt][1] * inv0);
            *(float2*)(o1 + nt * 8) = make_float2(cA[nt][2] * inv1, cA[nt][3] * inv1);
            *(float2*)(o2 + nt * 8) = make_float2(cB[nt][0] * inv2, cB[nt][1] * inv2);
            *(float2*)(o3 + nt * 8) = make_float2(cB[nt][2] * inv3, cB[nt][3] * inv3);
        }
    }
}

// ---------------------------------------------------------------------------
extern "C" void kernel_launch(void* const* d_in, const int* in_sizes, int n_in,
                              void* d_out, int out_size)
{
    const float* x    = (const float*)d_in[0];   // (8,2048,128) f32
    const int*   A    = (const int*)d_in[1];     // (2048,2048) i32
    const float* W    = (const float*)d_in[2];   // (128,64) f32
    const float* attn = (const float*)d_in[3];   // (128,1) f32
    float* out = (float*)d_out;                  // (8,2048,64) f32

    const int wh_smem = (64 * 132 + 128 * 72 + 256) * 4;   // 71680 B
    cudaFuncSetAttribute(k_wh, cudaFuncAttributeMaxDynamicSharedMemorySize, wh_smem);
    cudaFuncSetAttribute(k_gat, cudaFuncAttributeMaxDynamicSharedMemorySize, GAT_SMEM);

    k_wh  <<<BB * NN / 64, 256, wh_smem>>>(x, W, attn);
    k_mask<<<NN * NN / 1024, 256>>>(A);
    k_gat <<<BB * (NN / 128), 512, GAT_SMEM>>>(out);
}